// round 3
// baseline (speedup 1.0000x reference)
#include <cuda_runtime.h>
#include <cuda_fp16.h>
#include <math.h>

// Problem constants
#define NNODE 50000
#define NEDGE 800000
#define FIN 128
#define COUT 128   // NH*FOUT
#define NH 4

#define PROJ_WARPS 8
#define NPW 8            // nodes per warp per iteration
#define SCAN_BLK 1024
#define NSCAN_BLKS ((NNODE + SCAN_BLK - 1) / SCAN_BLK)   // 49

// ---------------- device scratch (no allocations allowed) ----------------
__device__ __half g_src_proj_h[NNODE * COUT];      // 12.8 MB (fp16)
__device__ float4 g_scores_src[NNODE];
__device__ float4 g_scores_trg[NNODE];
__device__ int    g_count[NNODE];
__device__ int    g_offsets[NNODE + 1];
__device__ int    g_blocksum[NSCAN_BLKS];
__device__ int    g_blockcarry[NSCAN_BLKS];
__device__ int    g_edge_rank[NEDGE];
__device__ float4 g_edge_exp[NEDGE];               // 12.8 MB
__device__ int    g_sorted_si[NEDGE];
__device__ float4 g_sorted_exp[NEDGE];             // 12.8 MB
__device__ float  g_Vt[FIN * NH];

// ---------------- kernels ----------------

__global__ void zero_kernel() {
    int i = blockIdx.x * blockDim.x + threadIdx.x;
    int stride = gridDim.x * blockDim.x;
    for (int k = i; k < NNODE; k += stride) g_count[k] = 0;
}

// Vt[f,h] = sum_j Wt[f, h*32+j] * a_trg[h, j]
__global__ void fold_kernel(const float* __restrict__ Wt,
                            const float* __restrict__ a_trg) {
    int f = threadIdx.x;  // 128 threads
    #pragma unroll
    for (int h = 0; h < NH; h++) {
        float s = 0.0f;
        #pragma unroll
        for (int j = 0; j < 32; j++)
            s += Wt[f * COUT + h * 32 + j] * a_trg[h * 32 + j];
        g_Vt[f * NH + h] = s;
    }
}

// scores_trg = trg @ Vt   (warp per node)
__global__ void strg_kernel(const float* __restrict__ trg) {
    __shared__ float Vsh[FIN * NH];
    for (int i = threadIdx.x; i < FIN * NH; i += blockDim.x) Vsh[i] = g_Vt[i];
    __syncthreads();

    int gwarp = (blockIdx.x * blockDim.x + threadIdx.x) >> 5;
    int lane = threadIdx.x & 31;
    if (gwarp >= NNODE) return;

    float4 xv = ((const float4*)(trg + (size_t)gwarp * FIN))[lane];
    int f0 = lane * 4;
    float a0, a1, a2, a3;
    a0 = xv.x * Vsh[(f0+0)*4+0] + xv.y * Vsh[(f0+1)*4+0] + xv.z * Vsh[(f0+2)*4+0] + xv.w * Vsh[(f0+3)*4+0];
    a1 = xv.x * Vsh[(f0+0)*4+1] + xv.y * Vsh[(f0+1)*4+1] + xv.z * Vsh[(f0+2)*4+1] + xv.w * Vsh[(f0+3)*4+1];
    a2 = xv.x * Vsh[(f0+0)*4+2] + xv.y * Vsh[(f0+1)*4+2] + xv.z * Vsh[(f0+2)*4+2] + xv.w * Vsh[(f0+3)*4+2];
    a3 = xv.x * Vsh[(f0+0)*4+3] + xv.y * Vsh[(f0+1)*4+3] + xv.z * Vsh[(f0+2)*4+3] + xv.w * Vsh[(f0+3)*4+3];
    #pragma unroll
    for (int o = 16; o > 0; o >>= 1) {
        a0 += __shfl_xor_sync(0xffffffffu, a0, o);
        a1 += __shfl_xor_sync(0xffffffffu, a1, o);
        a2 += __shfl_xor_sync(0xffffffffu, a2, o);
        a3 += __shfl_xor_sync(0xffffffffu, a3, o);
    }
    if (lane == 0) g_scores_trg[gwarp] = make_float4(a0, a1, a2, a3);
}

// src_proj = src @ Ws (register-blocked), fused scores_src epilogue.
// Output stored fp16 (consumed only by agg gather).
__global__ void proj_kernel(const float* __restrict__ src,
                            const float* __restrict__ Ws,
                            const float* __restrict__ a_src) {
    extern __shared__ float sh[];
    float* Wsh = sh;                        // 128*128
    float* ash = Wsh + FIN * COUT;          // 128
    float* xsh = ash + COUT;                // PROJ_WARPS * NPW * FIN

    {
        const float4* w4 = (const float4*)Ws;
        float4* s4 = (float4*)Wsh;
        for (int i = threadIdx.x; i < FIN * COUT / 4; i += blockDim.x) s4[i] = w4[i];
        for (int i = threadIdx.x; i < COUT; i += blockDim.x) ash[i] = a_src[i];
    }
    __syncthreads();

    int lane = threadIdx.x & 31;
    int w = threadIdx.x >> 5;
    float* myx = xsh + w * (NPW * FIN);

    const int ngroups = NNODE / NPW;         // 6250 (exact)
    int group = blockIdx.x * PROJ_WARPS + w;
    int gstride = gridDim.x * PROJ_WARPS;

    for (int g = group; g < ngroups; g += gstride) {
        int n0 = g * NPW;
        #pragma unroll
        for (int r = 0; r < NPW; r++) {
            float4 xv = ((const float4*)(src + (size_t)(n0 + r) * FIN))[lane];
            ((float4*)(myx + r * FIN))[lane] = xv;
        }
        __syncwarp();

        float acc[NPW][4];
        #pragma unroll
        for (int r = 0; r < NPW; r++) { acc[r][0]=0.f; acc[r][1]=0.f; acc[r][2]=0.f; acc[r][3]=0.f; }

        #pragma unroll 4
        for (int f = 0; f < FIN; f++) {
            float4 wv = ((const float4*)(Wsh + f * COUT))[lane];
            #pragma unroll
            for (int r = 0; r < NPW; r++) {
                float xf = myx[r * FIN + f];
                acc[r][0] += xf * wv.x;
                acc[r][1] += xf * wv.y;
                acc[r][2] += xf * wv.z;
                acc[r][3] += xf * wv.w;
            }
        }

        int h = lane >> 3;
        int fi = (lane & 7) * 4;
        float c0 = ash[h * 32 + fi + 0];
        float c1 = ash[h * 32 + fi + 1];
        float c2 = ash[h * 32 + fi + 2];
        float c3 = ash[h * 32 + fi + 3];

        #pragma unroll
        for (int r = 0; r < NPW; r++) {
            int n = n0 + r;
            // fp16 store: cols 4*lane .. 4*lane+3 as two half2 (uint2, 8B) -> coalesced
            __half2 lo = __floats2half2_rn(acc[r][0], acc[r][1]);
            __half2 hi = __floats2half2_rn(acc[r][2], acc[r][3]);
            uint2 pk;
            pk.x = *(unsigned int*)&lo;
            pk.y = *(unsigned int*)&hi;
            ((uint2*)(g_src_proj_h + (size_t)n * COUT))[lane] = pk;

            float p = acc[r][0]*c0 + acc[r][1]*c1 + acc[r][2]*c2 + acc[r][3]*c3;
            p += __shfl_xor_sync(0xffffffffu, p, 4);
            p += __shfl_xor_sync(0xffffffffu, p, 2);
            p += __shfl_xor_sync(0xffffffffu, p, 1);
            if ((lane & 7) == 0) ((float*)g_scores_src)[n * 4 + h] = p;
        }
        __syncwarp();
    }
}

__device__ __forceinline__ float lrelu_exp(float s) {
    float l = s > 0.0f ? s : 0.2f * s;
    return expf(l);
}

// pass 1: per-edge exp (stored), rank via count atomic
__global__ void edge1_kernel(const int* __restrict__ ei) {
    int e = blockIdx.x * blockDim.x + threadIdx.x;
    if (e >= NEDGE) return;
    int si = ei[e];
    int ti = ei[NEDGE + e];
    float4 ss = g_scores_src[si];
    float4 st = g_scores_trg[ti];
    float4 ex;
    ex.x = lrelu_exp(ss.x + st.x);
    ex.y = lrelu_exp(ss.y + st.y);
    ex.z = lrelu_exp(ss.z + st.z);
    ex.w = lrelu_exp(ss.w + st.w);
    g_edge_exp[e] = ex;
    g_edge_rank[e] = atomicAdd(&g_count[ti], 1);
}

// two-level scan
__global__ void scanA_kernel() {
    __shared__ int sh[SCAN_BLK];
    int tid = threadIdx.x;
    int gi = blockIdx.x * SCAN_BLK + tid;
    int v = (gi < NNODE) ? g_count[gi] : 0;
    sh[tid] = v;
    __syncthreads();
    #pragma unroll
    for (int off = 1; off < SCAN_BLK; off <<= 1) {
        int t = (tid >= off) ? sh[tid - off] : 0;
        __syncthreads();
        sh[tid] += t;
        __syncthreads();
    }
    if (gi < NNODE) g_offsets[gi + 1] = sh[tid];
    if (tid == SCAN_BLK - 1) g_blocksum[blockIdx.x] = sh[tid];
}

__global__ void scanB_kernel() {
    if (threadIdx.x == 0) {
        int c = 0;
        for (int b = 0; b < NSCAN_BLKS; b++) {
            g_blockcarry[b] = c;
            c += g_blocksum[b];
        }
        g_offsets[0] = 0;
    }
}

__global__ void scanC_kernel() {
    int tid = threadIdx.x;
    int gi = blockIdx.x * SCAN_BLK + tid;
    if (blockIdx.x == 0) return;
    if (gi < NNODE) g_offsets[gi + 1] += g_blockcarry[blockIdx.x];
}

// pass 2: pure permutation into CSR order
__global__ void edge2_kernel(const int* __restrict__ ei) {
    int e = blockIdx.x * blockDim.x + threadIdx.x;
    if (e >= NEDGE) return;
    int si = ei[e];
    int ti = ei[NEDGE + e];
    int pos = g_offsets[ti] + g_edge_rank[e];
    g_sorted_si[pos] = si;
    g_sorted_exp[pos] = g_edge_exp[e];
}

// aggregation: warp per target node; fp16 gather, 4-deep load-first pipeline.
// Layout per lane:
//   load1: half2 at row*64 + lane      -> cols 2l,2l+1     head = l<16 ? 0 : 1
//   load2: half2 at row*64 + 32 + lane -> cols 64+2l,65+2l head = l<16 ? 2 : 3
__global__ void agg_kernel(float* __restrict__ out) {
    int gwarp = (blockIdx.x * blockDim.x + threadIdx.x) >> 5;
    int lane = threadIdx.x & 31;
    if (gwarp >= NNODE) return;

    int s = g_offsets[gwarp];
    int e2 = g_offsets[gwarp + 1];

    const __half2* hsp = (const __half2*)g_src_proj_h;
    bool lowHalf = (lane < 16);

    float2 accA = make_float2(0.f, 0.f);
    float2 accB = make_float2(0.f, 0.f);
    float d0 = 0.f, d1 = 0.f, d2 = 0.f, d3 = 0.f;

    int i = s;
    for (; i + 4 <= e2; i += 4) {
        // issue all loads first (deep MLP)
        int si0 = g_sorted_si[i+0];
        int si1 = g_sorted_si[i+1];
        int si2 = g_sorted_si[i+2];
        int si3 = g_sorted_si[i+3];
        float4 ex0 = g_sorted_exp[i+0];
        float4 ex1 = g_sorted_exp[i+1];
        float4 ex2 = g_sorted_exp[i+2];
        float4 ex3 = g_sorted_exp[i+3];
        __half2 vA0 = hsp[(size_t)si0*64 + lane];
        __half2 vB0 = hsp[(size_t)si0*64 + 32 + lane];
        __half2 vA1 = hsp[(size_t)si1*64 + lane];
        __half2 vB1 = hsp[(size_t)si1*64 + 32 + lane];
        __half2 vA2 = hsp[(size_t)si2*64 + lane];
        __half2 vB2 = hsp[(size_t)si2*64 + 32 + lane];
        __half2 vA3 = hsp[(size_t)si3*64 + lane];
        __half2 vB3 = hsp[(size_t)si3*64 + 32 + lane];

        float wA0 = lowHalf ? ex0.x : ex0.y, wB0 = lowHalf ? ex0.z : ex0.w;
        float wA1 = lowHalf ? ex1.x : ex1.y, wB1 = lowHalf ? ex1.z : ex1.w;
        float wA2 = lowHalf ? ex2.x : ex2.y, wB2 = lowHalf ? ex2.z : ex2.w;
        float wA3 = lowHalf ? ex3.x : ex3.y, wB3 = lowHalf ? ex3.z : ex3.w;

        float2 f;
        f = __half22float2(vA0); accA.x += wA0*f.x; accA.y += wA0*f.y;
        f = __half22float2(vB0); accB.x += wB0*f.x; accB.y += wB0*f.y;
        f = __half22float2(vA1); accA.x += wA1*f.x; accA.y += wA1*f.y;
        f = __half22float2(vB1); accB.x += wB1*f.x; accB.y += wB1*f.y;
        f = __half22float2(vA2); accA.x += wA2*f.x; accA.y += wA2*f.y;
        f = __half22float2(vB2); accB.x += wB2*f.x; accB.y += wB2*f.y;
        f = __half22float2(vA3); accA.x += wA3*f.x; accA.y += wA3*f.y;
        f = __half22float2(vB3); accB.x += wB3*f.x; accB.y += wB3*f.y;

        d0 += ex0.x + ex1.x + ex2.x + ex3.x;
        d1 += ex0.y + ex1.y + ex2.y + ex3.y;
        d2 += ex0.z + ex1.z + ex2.z + ex3.z;
        d3 += ex0.w + ex1.w + ex2.w + ex3.w;
    }
    for (; i < e2; i++) {
        int si = g_sorted_si[i];
        float4 ex = g_sorted_exp[i];
        __half2 vA = hsp[(size_t)si*64 + lane];
        __half2 vB = hsp[(size_t)si*64 + 32 + lane];
        float wA = lowHalf ? ex.x : ex.y;
        float wB = lowHalf ? ex.z : ex.w;
        float2 f;
        f = __half22float2(vA); accA.x += wA*f.x; accA.y += wA*f.y;
        f = __half22float2(vB); accB.x += wB*f.x; accB.y += wB*f.y;
        d0 += ex.x; d1 += ex.y; d2 += ex.z; d3 += ex.w;
    }

    float r0 = 1.0f / (d0 + 1e-16f);
    float r1 = 1.0f / (d1 + 1e-16f);
    float r2 = 1.0f / (d2 + 1e-16f);
    float r3 = 1.0f / (d3 + 1e-16f);

    float rA = lowHalf ? r0 : r1;
    float rB = lowHalf ? r2 : r3;

    float2* o = (float2*)(out + (size_t)gwarp * COUT);
    o[lane]      = make_float2(accA.x * rA, accA.y * rA);   // cols 2l, 2l+1
    o[32 + lane] = make_float2(accB.x * rB, accB.y * rB);   // cols 64+2l, 65+2l
}

// ---------------- launch ----------------

extern "C" void kernel_launch(void* const* d_in, const int* in_sizes, int n_in,
                              void* d_out, int out_size) {
    const float* trg   = (const float*)d_in[0];
    const float* src   = (const float*)d_in[1];
    const int*   ei    = (const int*)d_in[2];
    const float* Wt    = (const float*)d_in[3];
    const float* Ws    = (const float*)d_in[4];
    const float* a_src = (const float*)d_in[5];
    const float* a_trg = (const float*)d_in[6];
    float* out = (float*)d_out;

    const int PROJ_BLOCK = PROJ_WARPS * 32;  // 256
    size_t proj_smem = (size_t)(FIN * COUT + COUT + PROJ_WARPS * NPW * FIN) * sizeof(float);
    cudaFuncSetAttribute(proj_kernel, cudaFuncAttributeMaxDynamicSharedMemorySize,
                         (int)proj_smem);

    zero_kernel<<<64, 256>>>();
    fold_kernel<<<1, 128>>>(Wt, a_trg);

    {
        int blocks = (NNODE * 32 + 255) / 256;
        strg_kernel<<<blocks, 256>>>(trg);
    }

    proj_kernel<<<296, PROJ_BLOCK, proj_smem>>>(src, Ws, a_src);

    {
        int blocks = (NEDGE + 255) / 256;
        edge1_kernel<<<blocks, 256>>>(ei);
    }

    scanA_kernel<<<NSCAN_BLKS, SCAN_BLK>>>();
    scanB_kernel<<<1, 32>>>();
    scanC_kernel<<<NSCAN_BLKS, SCAN_BLK>>>();

    {
        int blocks = (NEDGE + 255) / 256;
        edge2_kernel<<<blocks, 256>>>(ei);
    }

    {
        int blocks = (NNODE * 32 + 255) / 256;
        agg_kernel<<<blocks, 256>>>(out);
    }
}